// round 6
// baseline (speedup 1.0000x reference)
#include <cuda_runtime.h>
#include <cstdint>

#define BN 64
#define BD 512
#define BB 16

// ---------------------------------------------------------------------------
// Compile-time structure table.
// Entry = i1 | (i2<<10) | 0x40000000 for masked (i,j): content = max(L[i1],L[i2])
// over a 7-level sparse max table; -1 for unmasked.
// ---------------------------------------------------------------------------
struct TblT { int v[4096]; };

constexpr int ilog2c(int v) { int l = 0; while ((1 << (l + 1)) <= v) l++; return l; }

constexpr int pack_entry_c(int a, int b) {
    int len = b - a;
    int l = ilog2c(len);
    const int off[7] = {0, 64, 127, 188, 245, 294, 327};
    int i1 = off[l] + a;
    int i2 = off[l] + b - (1 << l);
    return i1 | (i2 << 10) | 0x40000000;
}

constexpr TblT make_tbl() {
    TblT t{};
    for (int i = 0; i < 4096; i++) t.v[i] = -1;
    int lo[64] = {}, hi[64] = {};
    for (int p = 0; p < 64; p++) {
        lo[p] = p; hi[p] = p + 1;
        t.v[p * 64 + p] = pack_entry_c(p, p + 1);
    }
    int len = 64, stride = 1, offset = 0;
    const int counts[3] = {15, 8, 8};
    for (int ci = 0; ci < 3; ci++) {
        for (int tt = 0; tt < counts[ci]; tt++) {
            offset += stride;
            int k = (ci == 0 || tt > 0) ? 2 : 3;
            int s = (k == 2) ? 1 : 2;
            int nl = (len - k) / s + 1;
            for (int p = 0; p < nl; p++) {
                int a = lo[p * s];
                int b = hi[p * s + k - 1];
                lo[p] = a; hi[p] = b;
                int i = p * stride, j = i + offset;
                t.v[i * 64 + j] = pack_entry_c(a, b);
            }
            len = nl;
        }
        stride *= 2;
    }
    return t;
}

constexpr TblT HOST_TBL = make_tbl();
__device__ const TblT g_tbl = HOST_TBL;

// Scratch (static device globals — no allocations)
__device__ float d_part[2 * BB * 64 * 1024];  // K-split partial sums (no bias)
__device__ float d_factor[BB * 4096];         // 1 + softmax weights

// ---------------------------------------------------------------------------
// Kernel 1: K-split GEMM. partial[ks][b][n][o] = sum_{k in ks-half} x[b,k,n]*W[o,k]
// o<512 -> w_v ; o>=512 -> w_c rows [0,512). Bias is added later in attn.
// Grid (16 o-tiles, 16 b, 2 ksplit), 256 threads, 64x64 tile, 4x4/thread,
// double-buffered smem (one sync per k-tile).
// ---------------------------------------------------------------------------
__global__ __launch_bounds__(256) void gemm_kernel(
    const float* __restrict__ x, const float* __restrict__ w_v,
    const float* __restrict__ w_c)
{
    int b  = blockIdx.y;
    int o0 = blockIdx.x * 64;
    int ks = blockIdx.z;
    const float* W = (o0 < 512) ? (w_v + (size_t)o0 * 512)
                                : (w_c + (size_t)(o0 - 512) * 512);
    W += ks * 256;
    const float* xb = x + (size_t)b * BD * BN + (size_t)ks * 256 * 64;

    __shared__ float As[2][16][64];
    __shared__ float Ws[2][16][68];

    int tid = threadIdx.x;
    int tx = tid & 15, ty = tid >> 4;
    float acc[4][4];
#pragma unroll
    for (int r = 0; r < 4; r++)
#pragma unroll
        for (int c = 0; c < 4; c++) acc[r][c] = 0.f;

    // prologue: load tile 0 into slot 0
    {
#pragma unroll
        for (int it = 0; it < 4; it++) {
            int e = tid + it * 256;
            int dd = e >> 6, n = e & 63;
            As[0][dd][n] = xb[(size_t)dd * 64 + n];
        }
        int o = tid >> 2, c4 = tid & 3;
        float4 v = *(const float4*)(W + (size_t)o * 512 + c4 * 4);
        Ws[0][c4 * 4 + 0][o] = v.x; Ws[0][c4 * 4 + 1][o] = v.y;
        Ws[0][c4 * 4 + 2][o] = v.z; Ws[0][c4 * 4 + 3][o] = v.w;
    }
    __syncthreads();

    for (int t = 0; t < 16; t++) {
        int s = t & 1, ns = s ^ 1;
        if (t < 15) {
            int kb = (t + 1) * 16;
#pragma unroll
            for (int it = 0; it < 4; it++) {
                int e = tid + it * 256;
                int dd = e >> 6, n = e & 63;
                As[ns][dd][n] = xb[(size_t)(kb + dd) * 64 + n];
            }
            int o = tid >> 2, c4 = tid & 3;
            float4 v = *(const float4*)(W + (size_t)o * 512 + kb + c4 * 4);
            Ws[ns][c4 * 4 + 0][o] = v.x; Ws[ns][c4 * 4 + 1][o] = v.y;
            Ws[ns][c4 * 4 + 2][o] = v.z; Ws[ns][c4 * 4 + 3][o] = v.w;
        }
#pragma unroll
        for (int kk = 0; kk < 16; kk++) {
            float4 a4 = *(const float4*)&As[s][kk][ty * 4];
            float4 b4 = *(const float4*)&Ws[s][kk][tx * 4];
            float av[4] = {a4.x, a4.y, a4.z, a4.w};
            float bw[4] = {b4.x, b4.y, b4.z, b4.w};
#pragma unroll
            for (int r = 0; r < 4; r++)
#pragma unroll
                for (int c = 0; c < 4; c++)
                    acc[r][c] += av[r] * bw[c];
        }
        __syncthreads();
    }

    float* dst = d_part + ((size_t)ks * BB + b) * 65536;
#pragma unroll
    for (int r = 0; r < 4; r++) {
        float4 o4 = make_float4(acc[r][0], acc[r][1], acc[r][2], acc[r][3]);
        *(float4*)&dst[(size_t)(ty * 4 + r) * 1024 + o0 + tx * 4] = o4;
    }
}

// ---------------------------------------------------------------------------
// Kernel 2: combine partials + bias on the fly; m2m = m_k @ m_q^T / 8,
// row softmax, factor = 1 + w.
// ---------------------------------------------------------------------------
__global__ __launch_bounds__(256) void attn_kernel(
    const float* __restrict__ b_v, const float* __restrict__ b_c)
{
    int b = blockIdx.y;
    int n0 = blockIdx.x * 16;
    __shared__ float Sk[16][33];
    __shared__ float Sq[32][68];
    __shared__ float sm[16][68];
    __shared__ float red[16];
    int tid = threadIdx.x;
    int tr = tid >> 4, tc = tid & 15;
    float acc[4] = {0, 0, 0, 0};
    const float* P0 = d_part + (size_t)b * 65536;
    const float* P1 = d_part + (size_t)(BB + b) * 65536;

    for (int kt = 0; kt < 512; kt += 32) {
#pragma unroll
        for (int it = 0; it < 2; it++) {
            int u = tid + it * 256;
            int r = u >> 5, kk = u & 31;
            size_t off = (size_t)(n0 + r) * 1024 + kt + kk;
            Sk[r][kk] = P0[off] + P1[off] + b_v[kt + kk];
        }
#pragma unroll
        for (int it = 0; it < 2; it++) {
            int u = tid + it * 256;
            int m = u >> 3, c4 = u & 7;
            size_t off = (size_t)m * 1024 + 512 + kt + c4 * 4;
            float4 v0 = *(const float4*)(P0 + off);
            float4 v1 = *(const float4*)(P1 + off);
            float4 vb = *(const float4*)(b_c + kt + c4 * 4);
            Sq[c4 * 4 + 0][m] = v0.x + v1.x + vb.x;
            Sq[c4 * 4 + 1][m] = v0.y + v1.y + vb.y;
            Sq[c4 * 4 + 2][m] = v0.z + v1.z + vb.z;
            Sq[c4 * 4 + 3][m] = v0.w + v1.w + vb.w;
        }
        __syncthreads();
#pragma unroll
        for (int kk = 0; kk < 32; kk++) {
            float a = Sk[tr][kk];
            float4 b4 = *(const float4*)&Sq[kk][tc * 4];
            acc[0] += a * b4.x; acc[1] += a * b4.y;
            acc[2] += a * b4.z; acc[3] += a * b4.w;
        }
        __syncthreads();
    }
#pragma unroll
    for (int c = 0; c < 4; c++) sm[tr][tc * 4 + c] = acc[c] * 0.125f;
    __syncthreads();
    if (tid < 16) {
        float mx = -1e30f;
        for (int m = 0; m < 64; m++) mx = fmaxf(mx, sm[tid][m]);
        red[tid] = mx;
    }
    __syncthreads();
    float mx = red[tr];
    float e[4];
#pragma unroll
    for (int c = 0; c < 4; c++) {
        e[c] = __expf(sm[tr][tc * 4 + c] - mx);
        sm[tr][tc * 4 + c] = e[c];
    }
    __syncthreads();
    if (tid < 16) {
        float s = 0.f;
        for (int m = 0; m < 64; m++) s += sm[tid][m];
        red[tid] = 1.f / s;
    }
    __syncthreads();
    float inv = red[tr];
#pragma unroll
    for (int c = 0; c < 4; c++)
        d_factor[(size_t)b * 4096 + (size_t)(n0 + tr) * 64 + tc * 4 + c] = 1.f + e[c] * inv;
}

// ---------------------------------------------------------------------------
// Kernel 3: one block per (b, 4 d-rows). lev tables for all 4 rows built in
// one parallel pass; 16 chunk-iterations (4 rows x 4 chunks of 1024 elems),
// double-buffered smem, each chunk drained by three 4 KB cp.async.bulk stores.
// Dynamic smem: 2*3*1024*4 = 24 KB.
// ---------------------------------------------------------------------------
#define SMEM_MAIN_BYTES (2 * 3 * 1024 * 4)

__global__ __launch_bounds__(256) void main_kernel(
    const float* __restrict__ x, float* __restrict__ out)
{
    __shared__ float lev[4][352];
    extern __shared__ float smb[];   // [2][3][1024]

    int b  = blockIdx.y;
    int d0 = blockIdx.x * 4;
    int tid = threadIdx.x;

    // Load 4 x-rows and build the 7-level sparse max tables in parallel.
    {
        int dg = tid >> 6, n = tid & 63;
        lev[dg][n] = x[((size_t)(b * BD + d0 + dg)) * 64 + n];
    }
    __syncthreads();
    const int offA[7] = {0, 64, 127, 188, 245, 294, 327};
#pragma unroll
    for (int l = 1; l < 7; l++) {
        int cnt = 65 - (1 << l);
        int half = 1 << (l - 1);
        if (tid < 4 * cnt) {
            int dg = tid / cnt, p = tid - dg * cnt;
            lev[dg][offA[l] + p] = fmaxf(lev[dg][offA[l - 1] + p],
                                         lev[dg][offA[l - 1] + p + half]);
        }
        __syncthreads();
    }

    const size_t mapsz = (size_t)BB * BD * 4096;
    const int4*   tblv = (const int4*)g_tbl.v;
    const float4* facv = (const float4*)(d_factor + (size_t)b * 4096);
    float* maskp = out + 3 * mapsz + (size_t)b * 4096;
    bool mask_blk = (blockIdx.x == 0);

    for (int it = 0; it < 16; it++) {
        int dg = it >> 2;
        int c  = it & 3;
        float* buf = smb + (it & 1) * 3072;
        const float* L = lev[dg];
        float* gBase = out + ((size_t)(b * BD + d0 + dg)) * 4096;

        if (it >= 2) {
            if (tid == 0)
                asm volatile("cp.async.bulk.wait_group.read 1;" ::: "memory");
            __syncthreads();
        }

        int q = c * 256 + tid;            // quad index (4 consecutive cols)
        int4 t4 = tblv[q];
        int i  = q >> 4;
        int j0 = (q & 15) << 2;
        float4* pB = (float4*)buf + tid;
        float4* pL = (float4*)buf + 256 + tid;
        float4* pC = (float4*)buf + 512 + tid;

        if ((t4.x & t4.y & t4.z & t4.w) < 0) {
            float4 z = make_float4(0.f, 0.f, 0.f, 0.f);
            *pB = z; *pL = z; *pC = z;
            if (mask_blk && dg == 0) __stcs((float4*)maskp + q, z);
        } else {
            float4 f4 = facv[q];
            float fs[4] = {f4.x, f4.y, f4.z, f4.w};
            int   ts[4] = {t4.x, t4.y, t4.z, t4.w};
            float xi = L[i];
            float bo[4], lc[4], co[4], mk[4];
#pragma unroll
            for (int cc = 0; cc < 4; cc++) {
                int t = ts[cc];
                if (t < 0) { bo[cc] = 0.f; lc[cc] = 0.f; co[cc] = 0.f; mk[cc] = 0.f; }
                else {
                    int j = j0 + cc;
                    float xj = L[j];
                    float xk = L[(i + j) >> 1];
                    float f  = fs[cc];
                    bo[cc] = (xi + xj) * 0.5f * f;
                    lc[cc] = (xi + xj + 0.5f * xk) * (1.f / 2.5f) * f;
                    co[cc] = fmaxf(L[t & 1023], L[(t >> 10) & 1023]) * f;
                    mk[cc] = 1.f;
                }
            }
            *pB = make_float4(bo[0], bo[1], bo[2], bo[3]);
            *pL = make_float4(lc[0], lc[1], lc[2], lc[3]);
            *pC = make_float4(co[0], co[1], co[2], co[3]);
            if (mask_blk && dg == 0)
                __stcs((float4*)maskp + q,
                       make_float4(mk[0], mk[1], mk[2], mk[3]));
        }
        __syncthreads();

        if (tid == 0) {
            uint32_t s0;
            asm("{ .reg .u64 t; cvta.to.shared.u64 t, %1; cvt.u32.u64 %0, t; }"
                : "=r"(s0) : "l"(buf));
            asm volatile("fence.proxy.async.shared::cta;" ::: "memory");
            asm volatile("cp.async.bulk.global.shared::cta.bulk_group [%0], [%1], %2;"
                         :: "l"(gBase + c * 1024), "r"(s0), "r"(4096) : "memory");
            asm volatile("cp.async.bulk.global.shared::cta.bulk_group [%0], [%1], %2;"
                         :: "l"(gBase + mapsz + c * 1024), "r"(s0 + 4096), "r"(4096) : "memory");
            asm volatile("cp.async.bulk.global.shared::cta.bulk_group [%0], [%1], %2;"
                         :: "l"(gBase + 2 * mapsz + c * 1024), "r"(s0 + 8192), "r"(4096) : "memory");
            asm volatile("cp.async.bulk.commit_group;" ::: "memory");
        }
    }

    // Keep the CTA (and its smem) alive until all bulk reads complete.
    if (tid == 0)
        asm volatile("cp.async.bulk.wait_group.read 0;" ::: "memory");
}

// ---------------------------------------------------------------------------
extern "C" void kernel_launch(void* const* d_in, const int* in_sizes, int n_in,
                              void* d_out, int out_size) {
    const float* x   = (const float*)d_in[0];
    const float* w_c = (const float*)d_in[1];
    const float* b_c = (const float*)d_in[2];
    const float* w_v = (const float*)d_in[3];
    const float* b_v = (const float*)d_in[4];
    float* out = (float*)d_out;

    gemm_kernel<<<dim3(16, 16, 2), 256>>>(x, w_v, w_c);
    attn_kernel<<<dim3(4, 16), 256>>>(b_v, b_c);
    main_kernel<<<dim3(128, 16), 256, SMEM_MAIN_BYTES>>>(x, out);
}